// round 17
// baseline (speedup 1.0000x reference)
#include <cuda_runtime.h>

// AdaPool2D, R15: structural ILP swing — 4 outputs/thread (16 channels,
// 16 independent chains, 16 upfront LDG.128 = MLP 16).
// R13 profile: issue 86.9% top binder, occ stuck ~67%, DRAM 75.8%.
// More warps didn't help; more ILP per thread is the remaining lever (the
// same direction that won R7->R8). Also: ta folded into paired rcp
// (u = ta*rab) saving 2 FMUL/channel. No launch bounds: let regs float
// (~80-96 expected); spills would show as L1% > 30.

#define BDIM 32
#define WDIM 224
#define HDIM 224
#define WO 112
#define HO 112
#define C4 16  // 64 channels / 4 floats per thread

__device__ __forceinline__ float adapool1(float a, float b, float c, float d,
                                          float u, float v, float na, float nb,
                                          float nc, float nd,
                                          float mk, float omk) {
    // u = 2*avg/(na*nb), v = 2*avg/(nc*nd) precomputed by caller.
    // --- exponential-maximum (softmax) pooling, no shift (inputs ~N(0,1)) ---
    float ea = __expf(a), eb = __expf(b), ec = __expf(c), ed = __expf(d);
    float den = (ea + eb) + (ec + ed);
    float num = fmaf(a, ea, fmaf(b, eb, fmaf(c, ec, d * ed)));

    // --- eDSCW: dsc = 2*avg*x/(x^2+avg^2) = (u*x)*n_other ---
    float fa = __expf((u * a) * nb);
    float fb = __expf((u * b) * na);
    float fc = __expf((v * c) * nd);
    float fd = __expf((v * d) * nc);
    float den2 = (fa + fb) + (fc + fd);
    float num2 = fmaf(a, fa, fmaf(b, fb, fmaf(c, fc, d * fd)));

    // paired softmax denominators folded into the blend:
    // result = rr * (mk*num*den2 + omk*num2*den),  rr = 1/(den*den2)
    float rr = __fdividef(1.0f, den * den2);
    float t2 = (omk * num2) * den;
    return rr * fmaf(mk * num, den2, t2);
}

__device__ __forceinline__ float ada_ch(float a, float b, float c, float d,
                                        float mk, float omk) {
    float s   = (a + b) + (c + d);
    float av2 = (s * s) * 0.0625f;   // avg^2
    float ta  = s * 0.5f;            // 2*avg
    float na = fmaf(a, a, av2);
    float nb = fmaf(b, b, av2);
    float nc = fmaf(c, c, av2);
    float nd = fmaf(d, d, av2);
    // paired reciprocals with ta folded in: u = 2*avg/(na*nb)
    float u = ta * __fdividef(1.0f, na * nb);
    float v = ta * __fdividef(1.0f, nc * nd);
    return adapool1(a, b, c, d, u, v, na, nb, nc, nd, mk, omk);
}

__device__ __forceinline__ float4 ada4(float4 p00, float4 p01, float4 p10, float4 p11,
                                       float mk, float omk) {
    float4 o;
    o.x = ada_ch(p00.x, p01.x, p10.x, p11.x, mk, omk);
    o.y = ada_ch(p00.y, p01.y, p10.y, p11.y, mk, omk);
    o.z = ada_ch(p00.z, p01.z, p10.z, p11.z, mk, omk);
    o.w = ada_ch(p00.w, p01.w, p10.w, p11.w, mk, omk);
    return o;
}

__global__ void adapool2d_kernel(const float4* __restrict__ in,
                                 const float* __restrict__ mask,
                                 float4* __restrict__ out) {
    // x covers (ho, c4): 112*16 = 1792 threads = 14 blocks of 128.
    // y = wo-quad (28): thread computes wo = 4*wq .. 4*wq+3. z = b.
    int i  = blockIdx.x * blockDim.x + threadIdx.x;
    int c4 = i & (C4 - 1);
    int ho = i >> 4;
    int wq = blockIdx.y;
    int b  = blockIdx.z;

    float mk  = __ldg(mask);
    float omk = 1.0f - mk;

    // int32 element offsets (input is 25.7M float4 < 2^31)
    int ibase = ((b * WDIM + 8 * wq) * HDIM + 2 * ho) * C4 + c4;
    const float4* base = in + ibase;
    const int rs = HDIM * C4;  // input w-row stride in float4 (3584)

    // 16 independent 16B streaming loads (four 2x2 windows): MLP=16
    float4 p00 = __ldcs(base);
    float4 p01 = __ldcs(base + C4);
    float4 p10 = __ldcs(base + rs);
    float4 p11 = __ldcs(base + rs + C4);
    float4 q00 = __ldcs(base + 2 * rs);
    float4 q01 = __ldcs(base + 2 * rs + C4);
    float4 q10 = __ldcs(base + 3 * rs);
    float4 q11 = __ldcs(base + 3 * rs + C4);
    float4 r00 = __ldcs(base + 4 * rs);
    float4 r01 = __ldcs(base + 4 * rs + C4);
    float4 r10 = __ldcs(base + 5 * rs);
    float4 r11 = __ldcs(base + 5 * rs + C4);
    float4 s00 = __ldcs(base + 6 * rs);
    float4 s01 = __ldcs(base + 6 * rs + C4);
    float4 s10 = __ldcs(base + 7 * rs);
    float4 s11 = __ldcs(base + 7 * rs + C4);

    float4 op = ada4(p00, p01, p10, p11, mk, omk);
    float4 oq = ada4(q00, q01, q10, q11, mk, omk);
    float4 orr = ada4(r00, r01, r10, r11, mk, omk);
    float4 os = ada4(s00, s01, s10, s11, mk, omk);

    int obase = ((b * WO + 4 * wq) * HO + ho) * C4 + c4;
    const int os_ = HO * C4;  // output w-row stride in float4 (1792)
    __stcs(out + obase, op);
    __stcs(out + obase + os_, oq);
    __stcs(out + obase + 2 * os_, orr);
    __stcs(out + obase + 3 * os_, os);
}

extern "C" void kernel_launch(void* const* d_in, const int* in_sizes, int n_in,
                              void* d_out, int out_size) {
    const float4* in   = (const float4*)d_in[0];
    const float*  mask = (const float*)d_in[1];
    float4*       out  = (float4*)d_out;

    dim3 block(128);
    dim3 grid(HO * C4 / 128, WO / 4, BDIM);  // (14, 28, 32)
    adapool2d_kernel<<<grid, block>>>(in, mask, out);
}